// round 14
// baseline (speedup 1.0000x reference)
#include <cuda_runtime.h>
#include <math.h>

#define BB 2
#define NN 4096
#define CD 64
#define NTH 128
#define MAXL 512

// output layout offsets (floats), concatenated in reference return order
#define EXPOFF  0ull
#define DISPOFF 24576ull
#define POFF    49152ull
#define CONFOFF 33603584ull
#define ENTOFF  33611776ull
#define SRCPOFF 33619968ull

// scratch
__device__ float g_ssq[BB*NN];
__device__ float g_tsq[BB*NN];
__device__ float g_tadd[BB*NN];    // lml_j - 0.1*tu_j folded
__device__ float g_smatch[BB*NN];
__device__ float g_sdt[(size_t)BB*NN*CD];
__device__ float g_tdt[(size_t)BB*NN*CD];

__device__ __forceinline__ float lin16(int v) {
    return (float)(2*v - 15) * (1.0f/15.0f);
}

__device__ __forceinline__ float warpRedMax(float v){
    #pragma unroll
    for (int o = 16; o; o >>= 1) v = fmaxf(v, __shfl_xor_sync(0xffffffffu, v, o));
    return v;
}
__device__ __forceinline__ float warpRedMin(float v){
    #pragma unroll
    for (int o = 16; o; o >>= 1) v = fminf(v, __shfl_xor_sync(0xffffffffu, v, o));
    return v;
}
__device__ __forceinline__ float warpRedSum(float v){
    #pragma unroll
    for (int o = 16; o; o >>= 1) v += __shfl_xor_sync(0xffffffffu, v, o);
    return v;
}

__device__ __forceinline__ float blockRedMax(float v, float* sred){
    v = warpRedMax(v);
    __syncthreads();
    if ((threadIdx.x & 31) == 0) sred[threadIdx.x >> 5] = v;
    __syncthreads();
    return fmaxf(fmaxf(sred[0], sred[1]), fmaxf(sred[2], sred[3]));
}
__device__ __forceinline__ float blockRedMin(float v, float* sred){
    v = warpRedMin(v);
    __syncthreads();
    if ((threadIdx.x & 31) == 0) sred[threadIdx.x >> 5] = v;
    __syncthreads();
    return fminf(fminf(sred[0], sred[1]), fminf(sred[2], sred[3]));
}

__global__ __launch_bounds__(256)
void kprep(const float* __restrict__ srcc, const float* __restrict__ tgtc,
           const float* __restrict__ sdesc, const float* __restrict__ tdesc,
           const float* __restrict__ sml, const float* __restrict__ tml,
           const float* __restrict__ tunc,
           float* __restrict__ out_srcpos)
{
    int idx = blockIdx.x * blockDim.x + threadIdx.x;
    if (idx >= BB*NN) return;
    int b = idx / NN, n = idx % NN;

    const float* scp = srcc + (size_t)b*3*NN;
    float s0 = scp[n], s1 = scp[NN+n], s2 = scp[2*NN+n];
    g_ssq[idx] = fmaf(s2, s2, fmaf(s1, s1, s0*s0));

    const float* tcp = tgtc + (size_t)b*3*NN;
    float t0 = tcp[n], t1 = tcp[NN+n], t2 = tcp[2*NN+n];
    g_tsq[idx] = fmaf(t2, t2, fmaf(t1, t1, t0*t0));

    const float* sm = sml + (size_t)b*2*NN;
    g_smatch[idx] = 1.0f / (1.0f + expf(sm[NN+n] - sm[n]));
    const float* tm = tml + (size_t)b*2*NN;
    float p0 = 1.0f / (1.0f + expf(tm[NN+n] - tm[n]));
    g_tadd[idx] = fmaxf(logf(p0), -20.0f) - 0.1f * tunc[idx];

    // transpose descriptors: (B,C,N) -> (B,N,C) row-major, float4 writes
    const float* sdp = sdesc + (size_t)b*CD*NN + n;
    const float* tdp = tdesc + (size_t)b*CD*NN + n;
    float4* so = (float4*)(g_sdt + (size_t)idx*CD);
    float4* to = (float4*)(g_tdt + (size_t)idx*CD);
    #pragma unroll
    for (int c4 = 0; c4 < CD/4; c4++) {
        float4 v, w;
        v.x = sdp[(size_t)(4*c4+0)*NN]; w.x = tdp[(size_t)(4*c4+0)*NN];
        v.y = sdp[(size_t)(4*c4+1)*NN]; w.y = tdp[(size_t)(4*c4+1)*NN];
        v.z = sdp[(size_t)(4*c4+2)*NN]; w.z = tdp[(size_t)(4*c4+2)*NN];
        v.w = sdp[(size_t)(4*c4+3)*NN]; w.w = tdp[(size_t)(4*c4+3)*NN];
        so[c4] = v;
        to[c4] = w;
    }

    // src_pos output (constant voxel grid broadcast)
    int d = n >> 8, h = (n >> 4) & 15, w = n & 15;
    out_srcpos[(size_t)idx*3 + 0] = lin16(d);
    out_srcpos[(size_t)idx*3 + 1] = lin16(h);
    out_srcpos[(size_t)idx*3 + 2] = lin16(w);
}

__global__ __launch_bounds__(NTH, 8)
void kmain(const float* __restrict__ srcc, const float* __restrict__ tgtc,
           float* __restrict__ out, float radThr)
{
    const int i = blockIdx.x;
    const int b = blockIdx.y;
    const int t = threadIdx.x;
    const int lane = t & 31;
    const int warp = t >> 5;
    const int bi = b*NN + i;

    __shared__ __align__(16) float s_sd[CD];
    __shared__ float s_red[4];
    __shared__ float s_red5[4][5];
    __shared__ int   s_m;
    __shared__ int   s_list[MAXL];
    __shared__ float s_dist[MAXL];
    __shared__ float s_scr[MAXL];

    // ---- phase 0: zero probs row early (fire-and-forget DRAM writes) ----
    float* prow = out + POFF + (size_t)bi * NN;
    {
        float4 z4 = make_float4(0.f, 0.f, 0.f, 0.f);
        float4* p4 = (float4*)prow;
        #pragma unroll
        for (int s = 0; s < 8; s++) p4[t + s*NTH] = z4;
    }

    if (t < CD) s_sd[t] = g_sdt[(size_t)bi*CD + t];
    if (t == 0) s_m = 0;

    float sc0 = srcc[(size_t)b*3*NN + i];
    float sc1 = srcc[(size_t)b*3*NN + NN + i];
    float sc2 = srcc[(size_t)b*3*NN + 2*NN + i];
    float ssq = g_ssq[bi];

    const float* tcp  = tgtc + (size_t)b*3*NN;
    const float* tsqp = g_tsq + b*NN;

    const float4* tc0 = (const float4*)tcp;
    const float4* tc1 = (const float4*)(tcp + NN);
    const float4* tc2 = (const float4*)(tcp + 2*NN);
    const float4* tq4 = (const float4*)tsqp;

    __syncthreads();   // s_m init before atomics

    // ---- phase 1: vectorized d2 sweep; inline atomic compaction ----
    // common-path threshold radThr is a constant: gather while streaming
    #pragma unroll 2
    for (int s = 0; s < 8; s++) {
        int g = t + s*NTH;
        float4 u0 = tc0[g], u1 = tc1[g], u2 = tc2[g], tq = tq4[g];
        float4 d2c;
        d2c.x = fmaxf(fmaf(-2.0f, fmaf(sc2,u2.x,fmaf(sc1,u1.x,sc0*u0.x)), ssq+tq.x), 1e-12f);
        d2c.y = fmaxf(fmaf(-2.0f, fmaf(sc2,u2.y,fmaf(sc1,u1.y,sc0*u0.y)), ssq+tq.y), 1e-12f);
        d2c.z = fmaxf(fmaf(-2.0f, fmaf(sc2,u2.z,fmaf(sc1,u1.z,sc0*u0.z)), ssq+tq.z), 1e-12f);
        d2c.w = fmaxf(fmaf(-2.0f, fmaf(sc2,u2.w,fmaf(sc1,u1.w,sc0*u0.w)), ssq+tq.w), 1e-12f);
        int j0 = g << 2;
        if (d2c.x <= radThr) { int p = atomicAdd(&s_m, 1); if (p < MAXL) { s_list[p] = j0;     s_dist[p] = sqrtf(d2c.x); } }
        if (d2c.y <= radThr) { int p = atomicAdd(&s_m, 1); if (p < MAXL) { s_list[p] = j0 + 1; s_dist[p] = sqrtf(d2c.y); } }
        if (d2c.z <= radThr) { int p = atomicAdd(&s_m, 1); if (p < MAXL) { s_list[p] = j0 + 2; s_dist[p] = sqrtf(d2c.z); } }
        if (d2c.w <= radThr) { int p = atomicAdd(&s_m, 1); if (p < MAXL) { s_list[p] = j0 + 3; s_dist[p] = sqrtf(d2c.w); } }
    }
    __syncthreads();   // s_list/s_dist/s_m/s_sd ready
    int cnt = s_m;

    // ---- phase 2: rare (cnt<24, ~0.7%): widen threshold, redo gather ----
    if (cnt < 24) {
        float last = -3.4e38f;
        int need = 24 - cnt;
        for (int k = 0; k < need; k++) {
            float lmin = 3.4e38f;
            for (int s = 0; s < 8; s++) {
                int g = t + s*NTH;
                float4 u0 = tc0[g], u1 = tc1[g], u2 = tc2[g], tq = tq4[g];
                float4 d2c;
                d2c.x = fmaxf(fmaf(-2.0f, fmaf(sc2,u2.x,fmaf(sc1,u1.x,sc0*u0.x)), ssq+tq.x), 1e-12f);
                d2c.y = fmaxf(fmaf(-2.0f, fmaf(sc2,u2.y,fmaf(sc1,u1.y,sc0*u0.y)), ssq+tq.y), 1e-12f);
                d2c.z = fmaxf(fmaf(-2.0f, fmaf(sc2,u2.z,fmaf(sc1,u1.z,sc0*u0.z)), ssq+tq.z), 1e-12f);
                d2c.w = fmaxf(fmaf(-2.0f, fmaf(sc2,u2.w,fmaf(sc1,u1.w,sc0*u0.w)), ssq+tq.w), 1e-12f);
                if (d2c.x > radThr && d2c.x > last) lmin = fminf(lmin, d2c.x);
                if (d2c.y > radThr && d2c.y > last) lmin = fminf(lmin, d2c.y);
                if (d2c.z > radThr && d2c.z > last) lmin = fminf(lmin, d2c.z);
                if (d2c.w > radThr && d2c.w > last) lmin = fminf(lmin, d2c.w);
            }
            last = blockRedMin(lmin, s_red);
        }
        float thrAll = fmaxf(radThr, last);

        __syncthreads();
        if (t == 0) s_m = 0;
        __syncthreads();
        for (int s = 0; s < 8; s++) {
            int g = t + s*NTH;
            float4 u0 = tc0[g], u1 = tc1[g], u2 = tc2[g], tq = tq4[g];
            float4 d2c;
            d2c.x = fmaxf(fmaf(-2.0f, fmaf(sc2,u2.x,fmaf(sc1,u1.x,sc0*u0.x)), ssq+tq.x), 1e-12f);
            d2c.y = fmaxf(fmaf(-2.0f, fmaf(sc2,u2.y,fmaf(sc1,u1.y,sc0*u0.y)), ssq+tq.y), 1e-12f);
            d2c.z = fmaxf(fmaf(-2.0f, fmaf(sc2,u2.z,fmaf(sc1,u1.z,sc0*u0.z)), ssq+tq.z), 1e-12f);
            d2c.w = fmaxf(fmaf(-2.0f, fmaf(sc2,u2.w,fmaf(sc1,u1.w,sc0*u0.w)), ssq+tq.w), 1e-12f);
            int j0 = g << 2;
            if (d2c.x <= thrAll) { int p = atomicAdd(&s_m, 1); if (p < MAXL) { s_list[p] = j0;     s_dist[p] = sqrtf(d2c.x); } }
            if (d2c.y <= thrAll) { int p = atomicAdd(&s_m, 1); if (p < MAXL) { s_list[p] = j0 + 1; s_dist[p] = sqrtf(d2c.y); } }
            if (d2c.z <= thrAll) { int p = atomicAdd(&s_m, 1); if (p < MAXL) { s_list[p] = j0 + 2; s_dist[p] = sqrtf(d2c.z); } }
            if (d2c.w <= thrAll) { int p = atomicAdd(&s_m, 1); if (p < MAXL) { s_list[p] = j0 + 3; s_dist[p] = sqrtf(d2c.w); } }
        }
        __syncthreads();
        cnt = s_m;
    }
    int m = min(cnt, MAXL);

    // ---- phase 4: 4-lane-cooperative sparse sim ----
    const float* tdb = g_tdt + (size_t)b*NN*CD;
    const float* tap = g_tadd + b*NN;
    {
        const int sub = lane >> 2;     // element slot 0..7
        const int q   = lane & 3;      // quarter within row
        const float4* sd4 = (const float4*)s_sd;
        for (int l0 = warp*8; l0 < m; l0 += 32) {
            int l = l0 + sub;
            float part = 0.f;
            int j = 0;
            if (l < m) {
                j = s_list[l];
                const float4* td4 = (const float4*)(tdb + (size_t)j*CD);
                #pragma unroll
                for (int c = 0; c < 4; c++) {
                    float4 x = sd4[c*4 + q];
                    float4 y = td4[c*4 + q];
                    part += fmaf(x.w, y.w, fmaf(x.z, y.z, fmaf(x.y, y.y, x.x*y.x)));
                }
            }
            part += __shfl_xor_sync(0xffffffffu, part, 2);
            part += __shfl_xor_sync(0xffffffffu, part, 1);
            if (q == 0 && l < m)
                s_scr[l] = part - s_dist[l] + tap[j];
        }
    }
    __syncthreads();

    // ---- phase 5: softmax stats (max, then one fused 5-sum reduction) ----
    float lm = -3.4e38f;
    for (int l = t; l < m; l += NTH) lm = fmaxf(lm, s_scr[l]);
    float M = blockRedMax(lm, s_red);

    const float tinv = 1.0f / 0.07f;
    float pS = 0.f, pW = 0.f, pV0 = 0.f, pV1 = 0.f, pV2 = 0.f;
    for (int l = t; l < m; l += NTH) {
        float z = (s_scr[l] - M) * tinv;
        float e = __expf(z);
        s_scr[l] = e;
        pS += e;
        pW += e * z;
        int j = s_list[l];
        pV0 += e * lin16(j >> 8);
        pV1 += e * lin16((j >> 4) & 15);
        pV2 += e * lin16(j & 15);
    }
    pS  = warpRedSum(pS);
    pW  = warpRedSum(pW);
    pV0 = warpRedSum(pV0);
    pV1 = warpRedSum(pV1);
    pV2 = warpRedSum(pV2);
    __syncthreads();
    if (lane == 0) {
        s_red5[warp][0] = pS;
        s_red5[warp][1] = pW;
        s_red5[warp][2] = pV0;
        s_red5[warp][3] = pV1;
        s_red5[warp][4] = pV2;
    }
    __syncthreads();
    float S  = (s_red5[0][0] + s_red5[1][0]) + (s_red5[2][0] + s_red5[3][0]);
    float W  = (s_red5[0][1] + s_red5[1][1]) + (s_red5[2][1] + s_red5[3][1]);
    float V0 = (s_red5[0][2] + s_red5[1][2]) + (s_red5[2][2] + s_red5[3][2]);
    float V1 = (s_red5[0][3] + s_red5[1][3]) + (s_red5[2][3] + s_red5[3][3]);
    float V2 = (s_red5[0][4] + s_red5[1][4]) + (s_red5[2][4] + s_red5[3][4]);

    float invS = 1.0f / S;

    // ---- phase 6: write normalized probs (scattered, few) + outputs ----
    for (int l = t; l < m; l += NTH) prow[s_list[l]] = s_scr[l] * invS;

    if (t == 0) {
        float e0 = V0 * invS, e1 = V1 * invS, e2 = V2 * invS;
        out[EXPOFF + (size_t)bi*3 + 0] = e0;
        out[EXPOFF + (size_t)bi*3 + 1] = e1;
        out[EXPOFF + (size_t)bi*3 + 2] = e2;
        float q0 = lin16(i >> 8), q1 = lin16((i >> 4) & 15), q2 = lin16(i & 15);
        out[DISPOFF + (size_t)b*3*NN + 0*NN + i] = e0 - q0;
        out[DISPOFF + (size_t)b*3*NN + 1*NN + i] = e1 - q1;
        out[DISPOFF + (size_t)b*3*NN + 2*NN + i] = e2 - q2;
        out[CONFOFF + bi] = g_smatch[bi] * invS;   // max prob is exactly 1/S
        out[ENTOFF  + bi] = logf(S) - W * invS;
    }
}

extern "C" void kernel_launch(void* const* d_in, const int* in_sizes, int n_in,
                              void* d_out, int out_size)
{
    const float* srcc  = (const float*)d_in[0];
    const float* tgtc  = (const float*)d_in[1];
    const float* sdesc = (const float*)d_in[2];
    const float* tdesc = (const float*)d_in[3];
    const float* sml   = (const float*)d_in[4];
    const float* tml   = (const float*)d_in[5];
    const float* tunc  = (const float*)d_in[7];
    float* out = (float*)d_out;

    // exact float boundary: largest v with sqrtf(v) <= 0.45f
    const float R = 0.45f;
    float radThr = R * R;
    while (sqrtf(radThr) > R) radThr = nextafterf(radThr, 0.0f);
    while (sqrtf(nextafterf(radThr, 1e30f)) <= R)
        radThr = nextafterf(radThr, 1e30f);

    kprep<<<(BB*NN + 255)/256, 256>>>(srcc, tgtc, sdesc, tdesc, sml, tml,
                                      tunc, out + SRCPOFF);
    dim3 grid(NN, BB);
    kmain<<<grid, NTH>>>(srcc, tgtc, out, radThr);
}

// round 15
// speedup vs baseline: 1.6697x; 1.6697x over previous
#include <cuda_runtime.h>
#include <math.h>

#define BB 2
#define NN 4096
#define CD 64
#define NTH 128
#define MAXL 512

// output layout offsets (floats), concatenated in reference return order
#define EXPOFF  0ull
#define DISPOFF 24576ull
#define POFF    49152ull
#define CONFOFF 33603584ull
#define ENTOFF  33611776ull
#define SRCPOFF 33619968ull

// scratch
__device__ float g_ssq[BB*NN];
__device__ float g_tsq[BB*NN];
__device__ float g_tadd[BB*NN];    // lml_j - 0.1*tu_j folded
__device__ float g_smatch[BB*NN];
__device__ float g_sdt[(size_t)BB*NN*CD];
__device__ float g_tdt[(size_t)BB*NN*CD];

__device__ __forceinline__ float lin16(int v) {
    return (float)(2*v - 15) * (1.0f/15.0f);
}

__device__ __forceinline__ float warpRedMax(float v){
    #pragma unroll
    for (int o = 16; o; o >>= 1) v = fmaxf(v, __shfl_xor_sync(0xffffffffu, v, o));
    return v;
}
__device__ __forceinline__ float warpRedMin(float v){
    #pragma unroll
    for (int o = 16; o; o >>= 1) v = fminf(v, __shfl_xor_sync(0xffffffffu, v, o));
    return v;
}
__device__ __forceinline__ float warpRedSum(float v){
    #pragma unroll
    for (int o = 16; o; o >>= 1) v += __shfl_xor_sync(0xffffffffu, v, o);
    return v;
}
__device__ __forceinline__ int warpRedSumI(int v){
    #pragma unroll
    for (int o = 16; o; o >>= 1) v += __shfl_xor_sync(0xffffffffu, v, o);
    return v;
}

__device__ __forceinline__ float blockRedMax(float v, float* sred){
    v = warpRedMax(v);
    __syncthreads();
    if ((threadIdx.x & 31) == 0) sred[threadIdx.x >> 5] = v;
    __syncthreads();
    return fmaxf(fmaxf(sred[0], sred[1]), fmaxf(sred[2], sred[3]));
}
__device__ __forceinline__ float blockRedMin(float v, float* sred){
    v = warpRedMin(v);
    __syncthreads();
    if ((threadIdx.x & 31) == 0) sred[threadIdx.x >> 5] = v;
    __syncthreads();
    return fminf(fminf(sred[0], sred[1]), fminf(sred[2], sred[3]));
}
__device__ __forceinline__ int blockRedSumI(int v, int* sred){
    v = warpRedSumI(v);
    __syncthreads();
    if ((threadIdx.x & 31) == 0) sred[threadIdx.x >> 5] = v;
    __syncthreads();
    return (sred[0] + sred[1]) + (sred[2] + sred[3]);
}

__global__ __launch_bounds__(256)
void kprep(const float* __restrict__ srcc, const float* __restrict__ tgtc,
           const float* __restrict__ sdesc, const float* __restrict__ tdesc,
           const float* __restrict__ sml, const float* __restrict__ tml,
           const float* __restrict__ tunc,
           float* __restrict__ out_srcpos)
{
    int idx = blockIdx.x * blockDim.x + threadIdx.x;
    if (idx >= BB*NN) return;
    int b = idx / NN, n = idx % NN;

    const float* scp = srcc + (size_t)b*3*NN;
    float s0 = scp[n], s1 = scp[NN+n], s2 = scp[2*NN+n];
    g_ssq[idx] = fmaf(s2, s2, fmaf(s1, s1, s0*s0));

    const float* tcp = tgtc + (size_t)b*3*NN;
    float t0 = tcp[n], t1 = tcp[NN+n], t2 = tcp[2*NN+n];
    g_tsq[idx] = fmaf(t2, t2, fmaf(t1, t1, t0*t0));

    const float* sm = sml + (size_t)b*2*NN;
    g_smatch[idx] = 1.0f / (1.0f + expf(sm[NN+n] - sm[n]));
    const float* tm = tml + (size_t)b*2*NN;
    float p0 = 1.0f / (1.0f + expf(tm[NN+n] - tm[n]));
    g_tadd[idx] = fmaxf(logf(p0), -20.0f) - 0.1f * tunc[idx];

    // transpose descriptors: (B,C,N) -> (B,N,C) row-major, float4 writes
    const float* sdp = sdesc + (size_t)b*CD*NN + n;
    const float* tdp = tdesc + (size_t)b*CD*NN + n;
    float4* so = (float4*)(g_sdt + (size_t)idx*CD);
    float4* to = (float4*)(g_tdt + (size_t)idx*CD);
    #pragma unroll
    for (int c4 = 0; c4 < CD/4; c4++) {
        float4 v, w;
        v.x = sdp[(size_t)(4*c4+0)*NN]; w.x = tdp[(size_t)(4*c4+0)*NN];
        v.y = sdp[(size_t)(4*c4+1)*NN]; w.y = tdp[(size_t)(4*c4+1)*NN];
        v.z = sdp[(size_t)(4*c4+2)*NN]; w.z = tdp[(size_t)(4*c4+2)*NN];
        v.w = sdp[(size_t)(4*c4+3)*NN]; w.w = tdp[(size_t)(4*c4+3)*NN];
        so[c4] = v;
        to[c4] = w;
    }

    // src_pos output (constant voxel grid broadcast)
    int d = n >> 8, h = (n >> 4) & 15, w = n & 15;
    out_srcpos[(size_t)idx*3 + 0] = lin16(d);
    out_srcpos[(size_t)idx*3 + 1] = lin16(h);
    out_srcpos[(size_t)idx*3 + 2] = lin16(w);
}

__global__ __launch_bounds__(NTH, 8)
void kmain(const float* __restrict__ srcc, const float* __restrict__ tgtc,
           float* __restrict__ out, float radThr)
{
    const int i = blockIdx.x;
    const int b = blockIdx.y;
    const int t = threadIdx.x;
    const int lane = t & 31;
    const int warp = t >> 5;
    const int bi = b*NN + i;

    __shared__ __align__(16) float s_v[NN];   // full d2 row (clamped)
    __shared__ __align__(16) float s_sd[CD];
    __shared__ float s_red[4];
    __shared__ float s_red5[4][5];
    __shared__ int   s_redi[4];
    __shared__ int   s_w[4];
    __shared__ int   s_list[MAXL];
    __shared__ float s_dist[MAXL];
    __shared__ float s_scr[MAXL];

    // ---- phase 0: zero probs row early (fire-and-forget DRAM writes) ----
    float* prow = out + POFF + (size_t)bi * NN;
    {
        float4 z4 = make_float4(0.f, 0.f, 0.f, 0.f);
        float4* p4 = (float4*)prow;
        #pragma unroll
        for (int s = 0; s < 8; s++) p4[t + s*NTH] = z4;
    }

    if (t < CD) s_sd[t] = g_sdt[(size_t)bi*CD + t];

    float sc0 = srcc[(size_t)b*3*NN + i];
    float sc1 = srcc[(size_t)b*3*NN + NN + i];
    float sc2 = srcc[(size_t)b*3*NN + 2*NN + i];
    float ssq = g_ssq[bi];

    const float* tcp  = tgtc + (size_t)b*3*NN;
    const float* tsqp = g_tsq + b*NN;

    const float4* tc0 = (const float4*)tcp;
    const float4* tc1 = (const float4*)(tcp + NN);
    const float4* tc2 = (const float4*)(tcp + 2*NN);
    const float4* tq4 = (const float4*)tsqp;
    float4* sv4 = (float4*)s_v;

    // ---- phase 1: vectorized d2 sweep (4 cols per group), mask inline ----
    unsigned amask = 0;
    #pragma unroll 2
    for (int s = 0; s < 8; s++) {
        int g = t + s*NTH;
        float4 u0 = tc0[g], u1 = tc1[g], u2 = tc2[g], tq = tq4[g];
        float4 d2c;
        d2c.x = fmaxf(fmaf(-2.0f, fmaf(sc2,u2.x,fmaf(sc1,u1.x,sc0*u0.x)), ssq+tq.x), 1e-12f);
        d2c.y = fmaxf(fmaf(-2.0f, fmaf(sc2,u2.y,fmaf(sc1,u1.y,sc0*u0.y)), ssq+tq.y), 1e-12f);
        d2c.z = fmaxf(fmaf(-2.0f, fmaf(sc2,u2.z,fmaf(sc1,u1.z,sc0*u0.z)), ssq+tq.z), 1e-12f);
        d2c.w = fmaxf(fmaf(-2.0f, fmaf(sc2,u2.w,fmaf(sc1,u1.w,sc0*u0.w)), ssq+tq.w), 1e-12f);
        sv4[g] = d2c;
        unsigned bb = 0;
        if (d2c.x <= radThr) bb |= 1u;
        if (d2c.y <= radThr) bb |= 2u;
        if (d2c.z <= radThr) bb |= 4u;
        if (d2c.w <= radThr) bb |= 8u;
        amask |= bb << (4*s);
    }
    __syncthreads();   // s_v / s_sd ready; protects s_redi
    int cnt = blockRedSumI(__popc(amask), s_redi);

    // ---- phase 2+3a: if radius count < 24 (rare, ~0.7%), widen the mask ----
    if (cnt < 24) {
        float last = -3.4e38f;
        int need = 24 - cnt;
        for (int k = 0; k < need; k++) {
            float lmin = 3.4e38f;
            #pragma unroll 2
            for (int s = 0; s < 8; s++) {
                float4 v = sv4[t + s*NTH];
                if (v.x > radThr && v.x > last) lmin = fminf(lmin, v.x);
                if (v.y > radThr && v.y > last) lmin = fminf(lmin, v.y);
                if (v.z > radThr && v.z > last) lmin = fminf(lmin, v.z);
                if (v.w > radThr && v.w > last) lmin = fminf(lmin, v.w);
            }
            last = blockRedMin(lmin, s_red);
        }
        float thrAll = fmaxf(radThr, last);
        amask = 0;
        #pragma unroll 2
        for (int s = 0; s < 8; s++) {
            float4 v = sv4[t + s*NTH];
            unsigned bb = 0;
            if (v.x <= thrAll) bb |= 1u;
            if (v.y <= thrAll) bb |= 2u;
            if (v.z <= thrAll) bb |= 4u;
            if (v.w <= thrAll) bb |= 8u;
            amask |= bb << (4*s);
        }
    }
    // common path (cnt >= 24): amask from phase 1 IS the allowed set

    // ---- phase 3b: scan compaction of allowed set ----
    int myc = __popc(amask);
    int incl = myc;
    #pragma unroll
    for (int o = 1; o < 32; o <<= 1) {
        int nbr = __shfl_up_sync(0xffffffffu, incl, o);
        if (lane >= o) incl += nbr;
    }
    __syncthreads();
    if (lane == 31) s_w[warp] = incl;
    __syncthreads();
    int base = incl - myc;
    #pragma unroll
    for (int w = 0; w < 4; w++)
        if (w < warp) base += s_w[w];
    int m = (s_w[0] + s_w[1]) + (s_w[2] + s_w[3]);
    if (m > MAXL) m = MAXL;

    unsigned rem = amask;
    while (rem) {
        int bt = __ffs(rem) - 1;
        rem &= rem - 1u;
        int j = ((t + (bt >> 2)*NTH) << 2) + (bt & 3);
        if (base < MAXL) {
            s_list[base] = j;
            s_dist[base] = sqrtf(s_v[j]);
        }
        base++;
    }
    __syncthreads();

    // ---- phase 4: 4-lane-cooperative sparse sim ----
    // 8 elements per warp per iteration; each group of 4 lanes covers one
    // 256B descriptor row; per instruction a group reads 64 consecutive bytes.
    const float* tdb = g_tdt + (size_t)b*NN*CD;
    const float* tap = g_tadd + b*NN;
    {
        const int sub = lane >> 2;     // element slot 0..7
        const int q   = lane & 3;      // quarter within row
        const float4* sd4 = (const float4*)s_sd;
        for (int l0 = warp*8; l0 < m; l0 += 32) {
            int l = l0 + sub;
            float part = 0.f;
            int j = 0;
            if (l < m) {
                j = s_list[l];
                const float4* td4 = (const float4*)(tdb + (size_t)j*CD);
                #pragma unroll
                for (int c = 0; c < 4; c++) {
                    float4 x = sd4[c*4 + q];
                    float4 y = td4[c*4 + q];
                    part += fmaf(x.w, y.w, fmaf(x.z, y.z, fmaf(x.y, y.y, x.x*y.x)));
                }
            }
            part += __shfl_xor_sync(0xffffffffu, part, 2);
            part += __shfl_xor_sync(0xffffffffu, part, 1);
            if (q == 0 && l < m)
                s_scr[l] = part - s_dist[l] + tap[j];
        }
    }
    __syncthreads();

    // ---- phase 5: softmax stats (max, then ONE fused 5-sum reduction) ----
    float lm = -3.4e38f;
    for (int l = t; l < m; l += NTH) lm = fmaxf(lm, s_scr[l]);
    float M = blockRedMax(lm, s_red);

    const float tinv = 1.0f / 0.07f;
    float pS = 0.f, pW = 0.f, pV0 = 0.f, pV1 = 0.f, pV2 = 0.f;
    for (int l = t; l < m; l += NTH) {
        float z = (s_scr[l] - M) * tinv;
        float e = __expf(z);
        s_scr[l] = e;
        pS += e;
        pW += e * z;
        int j = s_list[l];
        pV0 += e * lin16(j >> 8);
        pV1 += e * lin16((j >> 4) & 15);
        pV2 += e * lin16(j & 15);
    }
    pS  = warpRedSum(pS);
    pW  = warpRedSum(pW);
    pV0 = warpRedSum(pV0);
    pV1 = warpRedSum(pV1);
    pV2 = warpRedSum(pV2);
    __syncthreads();
    if (lane == 0) {
        s_red5[warp][0] = pS;
        s_red5[warp][1] = pW;
        s_red5[warp][2] = pV0;
        s_red5[warp][3] = pV1;
        s_red5[warp][4] = pV2;
    }
    __syncthreads();
    float S  = (s_red5[0][0] + s_red5[1][0]) + (s_red5[2][0] + s_red5[3][0]);
    float W  = (s_red5[0][1] + s_red5[1][1]) + (s_red5[2][1] + s_red5[3][1]);
    float V0 = (s_red5[0][2] + s_red5[1][2]) + (s_red5[2][2] + s_red5[3][2]);
    float V1 = (s_red5[0][3] + s_red5[1][3]) + (s_red5[2][3] + s_red5[3][3]);
    float V2 = (s_red5[0][4] + s_red5[1][4]) + (s_red5[2][4] + s_red5[3][4]);

    float invS = 1.0f / S;

    // ---- phase 6: write normalized probs (scattered, few) + outputs ----
    for (int l = t; l < m; l += NTH) prow[s_list[l]] = s_scr[l] * invS;

    if (t == 0) {
        float e0 = V0 * invS, e1 = V1 * invS, e2 = V2 * invS;
        out[EXPOFF + (size_t)bi*3 + 0] = e0;
        out[EXPOFF + (size_t)bi*3 + 1] = e1;
        out[EXPOFF + (size_t)bi*3 + 2] = e2;
        float q0 = lin16(i >> 8), q1 = lin16((i >> 4) & 15), q2 = lin16(i & 15);
        out[DISPOFF + (size_t)b*3*NN + 0*NN + i] = e0 - q0;
        out[DISPOFF + (size_t)b*3*NN + 1*NN + i] = e1 - q1;
        out[DISPOFF + (size_t)b*3*NN + 2*NN + i] = e2 - q2;
        out[CONFOFF + bi] = g_smatch[bi] * invS;   // max prob is exactly 1/S
        out[ENTOFF  + bi] = logf(S) - W * invS;
    }
}

extern "C" void kernel_launch(void* const* d_in, const int* in_sizes, int n_in,
                              void* d_out, int out_size)
{
    const float* srcc  = (const float*)d_in[0];
    const float* tgtc  = (const float*)d_in[1];
    const float* sdesc = (const float*)d_in[2];
    const float* tdesc = (const float*)d_in[3];
    const float* sml   = (const float*)d_in[4];
    const float* tml   = (const float*)d_in[5];
    const float* tunc  = (const float*)d_in[7];
    float* out = (float*)d_out;

    // exact float boundary: largest v with sqrtf(v) <= 0.45f
    const float R = 0.45f;
    float radThr = R * R;
    while (sqrtf(radThr) > R) radThr = nextafterf(radThr, 0.0f);
    while (sqrtf(nextafterf(radThr, 1e30f)) <= R)
        radThr = nextafterf(radThr, 1e30f);

    kprep<<<(BB*NN + 255)/256, 256>>>(srcc, tgtc, sdesc, tdesc, sml, tml,
                                      tunc, out + SRCPOFF);
    dim3 grid(NN, BB);
    kmain<<<grid, NTH>>>(srcc, tgtc, out, radThr);
}

// round 16
// speedup vs baseline: 1.6773x; 1.0045x over previous
#include <cuda_runtime.h>
#include <math.h>

#define BB 2
#define NN 4096
#define CD 64
#define NTH 128
#define MAXL 512

// output layout offsets (floats), concatenated in reference return order
#define EXPOFF  0ull
#define DISPOFF 24576ull
#define POFF    49152ull
#define CONFOFF 33603584ull
#define ENTOFF  33611776ull
#define SRCPOFF 33619968ull

// scratch
__device__ float g_ssq[BB*NN];
__device__ float g_tsq[BB*NN];
__device__ float g_tadd[BB*NN];    // lml_j - 0.1*tu_j folded
__device__ float g_smatch[BB*NN];
__device__ float g_sdt[(size_t)BB*NN*CD];
__device__ float g_tdt[(size_t)BB*NN*CD];

__device__ __forceinline__ float lin16(int v) {
    return (float)(2*v - 15) * (1.0f/15.0f);
}

__device__ __forceinline__ float warpRedMax(float v){
    #pragma unroll
    for (int o = 16; o; o >>= 1) v = fmaxf(v, __shfl_xor_sync(0xffffffffu, v, o));
    return v;
}
__device__ __forceinline__ float warpRedMin(float v){
    #pragma unroll
    for (int o = 16; o; o >>= 1) v = fminf(v, __shfl_xor_sync(0xffffffffu, v, o));
    return v;
}
__device__ __forceinline__ float warpRedSum(float v){
    #pragma unroll
    for (int o = 16; o; o >>= 1) v += __shfl_xor_sync(0xffffffffu, v, o);
    return v;
}
__device__ __forceinline__ int warpRedSumI(int v){
    #pragma unroll
    for (int o = 16; o; o >>= 1) v += __shfl_xor_sync(0xffffffffu, v, o);
    return v;
}

__device__ __forceinline__ float blockRedMax(float v, float* sred){
    v = warpRedMax(v);
    __syncthreads();
    if ((threadIdx.x & 31) == 0) sred[threadIdx.x >> 5] = v;
    __syncthreads();
    return fmaxf(fmaxf(sred[0], sred[1]), fmaxf(sred[2], sred[3]));
}
__device__ __forceinline__ float blockRedMin(float v, float* sred){
    v = warpRedMin(v);
    __syncthreads();
    if ((threadIdx.x & 31) == 0) sred[threadIdx.x >> 5] = v;
    __syncthreads();
    return fminf(fminf(sred[0], sred[1]), fminf(sred[2], sred[3]));
}
__device__ __forceinline__ int blockRedSumI(int v, int* sred){
    v = warpRedSumI(v);
    __syncthreads();
    if ((threadIdx.x & 31) == 0) sred[threadIdx.x >> 5] = v;
    __syncthreads();
    return (sred[0] + sred[1]) + (sred[2] + sred[3]);
}

__global__ __launch_bounds__(256)
void kprep(const float* __restrict__ srcc, const float* __restrict__ tgtc,
           const float* __restrict__ sdesc, const float* __restrict__ tdesc,
           const float* __restrict__ sml, const float* __restrict__ tml,
           const float* __restrict__ tunc,
           float* __restrict__ out_srcpos)
{
    int idx = blockIdx.x * blockDim.x + threadIdx.x;
    if (idx >= BB*NN) return;
    int b = idx / NN, n = idx % NN;

    const float* scp = srcc + (size_t)b*3*NN;
    float s0 = scp[n], s1 = scp[NN+n], s2 = scp[2*NN+n];
    g_ssq[idx] = fmaf(s2, s2, fmaf(s1, s1, s0*s0));

    const float* tcp = tgtc + (size_t)b*3*NN;
    float t0 = tcp[n], t1 = tcp[NN+n], t2 = tcp[2*NN+n];
    g_tsq[idx] = fmaf(t2, t2, fmaf(t1, t1, t0*t0));

    const float* sm = sml + (size_t)b*2*NN;
    g_smatch[idx] = 1.0f / (1.0f + expf(sm[NN+n] - sm[n]));
    const float* tm = tml + (size_t)b*2*NN;
    float p0 = 1.0f / (1.0f + expf(tm[NN+n] - tm[n]));
    g_tadd[idx] = fmaxf(logf(p0), -20.0f) - 0.1f * tunc[idx];

    // transpose descriptors: (B,C,N) -> (B,N,C) row-major, float4 writes
    const float* sdp = sdesc + (size_t)b*CD*NN + n;
    const float* tdp = tdesc + (size_t)b*CD*NN + n;
    float4* so = (float4*)(g_sdt + (size_t)idx*CD);
    float4* to = (float4*)(g_tdt + (size_t)idx*CD);
    #pragma unroll
    for (int c4 = 0; c4 < CD/4; c4++) {
        float4 v, w;
        v.x = sdp[(size_t)(4*c4+0)*NN]; w.x = tdp[(size_t)(4*c4+0)*NN];
        v.y = sdp[(size_t)(4*c4+1)*NN]; w.y = tdp[(size_t)(4*c4+1)*NN];
        v.z = sdp[(size_t)(4*c4+2)*NN]; w.z = tdp[(size_t)(4*c4+2)*NN];
        v.w = sdp[(size_t)(4*c4+3)*NN]; w.w = tdp[(size_t)(4*c4+3)*NN];
        so[c4] = v;
        to[c4] = w;
    }

    // src_pos output (constant voxel grid broadcast)
    int d = n >> 8, h = (n >> 4) & 15, w = n & 15;
    out_srcpos[(size_t)idx*3 + 0] = lin16(d);
    out_srcpos[(size_t)idx*3 + 1] = lin16(h);
    out_srcpos[(size_t)idx*3 + 2] = lin16(w);
}

__global__ __launch_bounds__(NTH, 8)
void kmain(const float* __restrict__ srcc, const float* __restrict__ tgtc,
           float* __restrict__ out, float radThr)
{
    const int i = blockIdx.x;
    const int b = blockIdx.y;
    const int t = threadIdx.x;
    const int lane = t & 31;
    const int warp = t >> 5;
    const int bi = b*NN + i;

    __shared__ __align__(16) float s_v[NN];   // v = tsq - 2*dot (d2 = v + ssq)
    __shared__ __align__(16) float s_sd[CD];
    __shared__ float s_red[4];
    __shared__ float s_red5[4][5];
    __shared__ int   s_redi[4];
    __shared__ int   s_w[4];
    __shared__ int   s_list[MAXL];
    __shared__ float s_dist[MAXL];
    __shared__ float s_scr[MAXL];

    // ---- phase 0: zero probs row early (fire-and-forget DRAM writes) ----
    float* prow = out + POFF + (size_t)bi * NN;
    {
        float4 z4 = make_float4(0.f, 0.f, 0.f, 0.f);
        float4* p4 = (float4*)prow;
        #pragma unroll
        for (int s = 0; s < 8; s++) p4[t + s*NTH] = z4;
    }

    if (t < CD) s_sd[t] = g_sdt[(size_t)bi*CD + t];

    float sc0 = srcc[(size_t)b*3*NN + i];
    float sc1 = srcc[(size_t)b*3*NN + NN + i];
    float sc2 = srcc[(size_t)b*3*NN + 2*NN + i];
    float ssq = g_ssq[bi];

    // v-domain: v = fmaf(m0,u0, fmaf(m1,u1, fmaf(m2,u2, tq))), d2 = v + ssq
    const float m0 = -2.0f * sc0, m1 = -2.0f * sc1, m2 = -2.0f * sc2;
    const float vthr = radThr - ssq;   // v <= vthr  <=>  in radius

    const float* tcp  = tgtc + (size_t)b*3*NN;
    const float* tsqp = g_tsq + b*NN;

    const float4* tc0 = (const float4*)tcp;
    const float4* tc1 = (const float4*)(tcp + NN);
    const float4* tc2 = (const float4*)(tcp + 2*NN);
    const float4* tq4 = (const float4*)tsqp;
    float4* sv4 = (float4*)s_v;

    // ---- phase 1: v-domain sweep (3 FFMA/element), mask inline ----
    unsigned amask = 0;
    #pragma unroll 2
    for (int s = 0; s < 8; s++) {
        int g = t + s*NTH;
        float4 u0 = tc0[g], u1 = tc1[g], u2 = tc2[g], tq = tq4[g];
        float4 v4;
        v4.x = fmaf(m0, u0.x, fmaf(m1, u1.x, fmaf(m2, u2.x, tq.x)));
        v4.y = fmaf(m0, u0.y, fmaf(m1, u1.y, fmaf(m2, u2.y, tq.y)));
        v4.z = fmaf(m0, u0.z, fmaf(m1, u1.z, fmaf(m2, u2.z, tq.z)));
        v4.w = fmaf(m0, u0.w, fmaf(m1, u1.w, fmaf(m2, u2.w, tq.w)));
        sv4[g] = v4;
        unsigned bb = 0;
        if (v4.x <= vthr) bb |= 1u;
        if (v4.y <= vthr) bb |= 2u;
        if (v4.z <= vthr) bb |= 4u;
        if (v4.w <= vthr) bb |= 8u;
        amask |= bb << (4*s);
    }
    __syncthreads();   // s_v / s_sd ready; protects s_redi
    int cnt = blockRedSumI(__popc(amask), s_redi);

    // ---- phase 2+3a: if radius count < 24 (rare, ~0.7%), widen the mask ----
    if (cnt < 24) {
        float last = -3.4e38f;
        int need = 24 - cnt;
        for (int k = 0; k < need; k++) {
            float lmin = 3.4e38f;
            #pragma unroll 2
            for (int s = 0; s < 8; s++) {
                float4 v = sv4[t + s*NTH];
                if (v.x > vthr && v.x > last) lmin = fminf(lmin, v.x);
                if (v.y > vthr && v.y > last) lmin = fminf(lmin, v.y);
                if (v.z > vthr && v.z > last) lmin = fminf(lmin, v.z);
                if (v.w > vthr && v.w > last) lmin = fminf(lmin, v.w);
            }
            last = blockRedMin(lmin, s_red);
        }
        float thrAll = fmaxf(vthr, last);
        amask = 0;
        #pragma unroll 2
        for (int s = 0; s < 8; s++) {
            float4 v = sv4[t + s*NTH];
            unsigned bb = 0;
            if (v.x <= thrAll) bb |= 1u;
            if (v.y <= thrAll) bb |= 2u;
            if (v.z <= thrAll) bb |= 4u;
            if (v.w <= thrAll) bb |= 8u;
            amask |= bb << (4*s);
        }
    }
    // common path (cnt >= 24): amask from phase 1 IS the allowed set

    // ---- phase 3b: scan compaction of allowed set ----
    int myc = __popc(amask);
    int incl = myc;
    #pragma unroll
    for (int o = 1; o < 32; o <<= 1) {
        int nbr = __shfl_up_sync(0xffffffffu, incl, o);
        if (lane >= o) incl += nbr;
    }
    __syncthreads();
    if (lane == 31) s_w[warp] = incl;
    __syncthreads();
    int base = incl - myc;
    #pragma unroll
    for (int w = 0; w < 4; w++)
        if (w < warp) base += s_w[w];
    int m = (s_w[0] + s_w[1]) + (s_w[2] + s_w[3]);
    if (m > MAXL) m = MAXL;

    unsigned rem = amask;
    while (rem) {
        int bt = __ffs(rem) - 1;
        rem &= rem - 1u;
        int j = ((t + (bt >> 2)*NTH) << 2) + (bt & 3);
        if (base < MAXL) {
            s_list[base] = j;
            s_dist[base] = sqrtf(fmaxf(s_v[j] + ssq, 1e-12f));
        }
        base++;
    }
    __syncthreads();

    // ---- phase 4: 4-lane-cooperative sparse sim ----
    // 8 elements per warp per iteration; each group of 4 lanes covers one
    // 256B descriptor row; per instruction a group reads 64 consecutive bytes.
    const float* tdb = g_tdt + (size_t)b*NN*CD;
    const float* tap = g_tadd + b*NN;
    {
        const int sub = lane >> 2;     // element slot 0..7
        const int q   = lane & 3;      // quarter within row
        const float4* sd4 = (const float4*)s_sd;
        for (int l0 = warp*8; l0 < m; l0 += 32) {
            int l = l0 + sub;
            float part = 0.f;
            int j = 0;
            if (l < m) {
                j = s_list[l];
                const float4* td4 = (const float4*)(tdb + (size_t)j*CD);
                #pragma unroll
                for (int c = 0; c < 4; c++) {
                    float4 x = sd4[c*4 + q];
                    float4 y = td4[c*4 + q];
                    part += fmaf(x.w, y.w, fmaf(x.z, y.z, fmaf(x.y, y.y, x.x*y.x)));
                }
            }
            part += __shfl_xor_sync(0xffffffffu, part, 2);
            part += __shfl_xor_sync(0xffffffffu, part, 1);
            if (q == 0 && l < m)
                s_scr[l] = part - s_dist[l] + tap[j];
        }
    }
    __syncthreads();

    // ---- phase 5: softmax stats (max, then ONE fused 5-sum reduction) ----
    float lm = -3.4e38f;
    for (int l = t; l < m; l += NTH) lm = fmaxf(lm, s_scr[l]);
    float M = blockRedMax(lm, s_red);

    const float tinv = 1.0f / 0.07f;
    float pS = 0.f, pW = 0.f, pV0 = 0.f, pV1 = 0.f, pV2 = 0.f;
    for (int l = t; l < m; l += NTH) {
        float z = (s_scr[l] - M) * tinv;
        float e = __expf(z);
        s_scr[l] = e;
        pS += e;
        pW += e * z;
        int j = s_list[l];
        pV0 += e * lin16(j >> 8);
        pV1 += e * lin16((j >> 4) & 15);
        pV2 += e * lin16(j & 15);
    }
    pS  = warpRedSum(pS);
    pW  = warpRedSum(pW);
    pV0 = warpRedSum(pV0);
    pV1 = warpRedSum(pV1);
    pV2 = warpRedSum(pV2);
    __syncthreads();
    if (lane == 0) {
        s_red5[warp][0] = pS;
        s_red5[warp][1] = pW;
        s_red5[warp][2] = pV0;
        s_red5[warp][3] = pV1;
        s_red5[warp][4] = pV2;
    }
    __syncthreads();
    float S  = (s_red5[0][0] + s_red5[1][0]) + (s_red5[2][0] + s_red5[3][0]);
    float W  = (s_red5[0][1] + s_red5[1][1]) + (s_red5[2][1] + s_red5[3][1]);
    float V0 = (s_red5[0][2] + s_red5[1][2]) + (s_red5[2][2] + s_red5[3][2]);
    float V1 = (s_red5[0][3] + s_red5[1][3]) + (s_red5[2][3] + s_red5[3][3]);
    float V2 = (s_red5[0][4] + s_red5[1][4]) + (s_red5[2][4] + s_red5[3][4]);

    float invS = 1.0f / S;

    // ---- phase 6: write normalized probs (scattered, few) + outputs ----
    for (int l = t; l < m; l += NTH) prow[s_list[l]] = s_scr[l] * invS;

    if (t == 0) {
        float e0 = V0 * invS, e1 = V1 * invS, e2 = V2 * invS;
        out[EXPOFF + (size_t)bi*3 + 0] = e0;
        out[EXPOFF + (size_t)bi*3 + 1] = e1;
        out[EXPOFF + (size_t)bi*3 + 2] = e2;
        float q0 = lin16(i >> 8), q1 = lin16((i >> 4) & 15), q2 = lin16(i & 15);
        out[DISPOFF + (size_t)b*3*NN + 0*NN + i] = e0 - q0;
        out[DISPOFF + (size_t)b*3*NN + 1*NN + i] = e1 - q1;
        out[DISPOFF + (size_t)b*3*NN + 2*NN + i] = e2 - q2;
        out[CONFOFF + bi] = g_smatch[bi] * invS;   // max prob is exactly 1/S
        out[ENTOFF  + bi] = logf(S) - W * invS;
    }
}

extern "C" void kernel_launch(void* const* d_in, const int* in_sizes, int n_in,
                              void* d_out, int out_size)
{
    const float* srcc  = (const float*)d_in[0];
    const float* tgtc  = (const float*)d_in[1];
    const float* sdesc = (const float*)d_in[2];
    const float* tdesc = (const float*)d_in[3];
    const float* sml   = (const float*)d_in[4];
    const float* tml   = (const float*)d_in[5];
    const float* tunc  = (const float*)d_in[7];
    float* out = (float*)d_out;

    // exact float boundary: largest v with sqrtf(v) <= 0.45f
    const float R = 0.45f;
    float radThr = R * R;
    while (sqrtf(radThr) > R) radThr = nextafterf(radThr, 0.0f);
    while (sqrtf(nextafterf(radThr, 1e30f)) <= R)
        radThr = nextafterf(radThr, 1e30f);

    kprep<<<(BB*NN + 255)/256, 256>>>(srcc, tgtc, sdesc, tdesc, sml, tml,
                                      tunc, out + SRCPOFF);
    dim3 grid(NN, BB);
    kmain<<<grid, NTH>>>(srcc, tgtc, out, radThr);
}